// round 7
// baseline (speedup 1.0000x reference)
#include <cuda_runtime.h>
#include <cuda_fp16.h>

#define N_NODES 100000
#define N_EDGES 1600000
#define HID 128
#define C_OUT 64
#define NB_SCAN 98  // ceil(100000/1024)

// ---- scratch (__device__ globals; allocation-free rule) ----
__device__ __align__(16) float g_dis[N_NODES];
__device__ int   g_cnt[N_NODES];
__device__ int   g_cursor[N_NODES];
__device__ int   g_incl[N_NODES];
__device__ int   g_part[128];
__device__ int   g_partx[128];
__device__ int   g_row_start[N_NODES + 1];
__device__ int   g_csr_src[N_EDGES];
__device__ __align__(16) float  g_csr_w[N_EDGES];
__device__ __align__(16) __half g_g0h[(size_t)N_NODES * HID];  // x @ W1 (fp16)
__device__ __align__(16) __half g_hh [(size_t)N_NODES * HID];  // h      (fp16)

// ---------- f32x2 helpers ----------
#define FMA2(d, a, b) asm("fma.rn.f32x2 %0, %1, %2, %0;" : "+l"(d) : "l"(a), "l"(b))
#define PACK_BB(d, f) asm("mov.b64 %0, {%1, %1};" : "=l"(d) : "f"(f))
#define UNPACK2(lo, hi, d) asm("mov.b64 {%0, %1}, %2;" : "=f"(lo), "=f"(hi) : "l"(d))

// ---------------- degree / CSR build ----------------
__global__ void k_zero_cnt() {
    int i = blockIdx.x * blockDim.x + threadIdx.x;
    if (i < N_NODES) g_cnt[i] = 0;
}

__global__ void k_hist(const int* __restrict__ ei) {
    int e = blockIdx.x * blockDim.x + threadIdx.x;
    if (e < N_EDGES) {
        unsigned d = (unsigned)ei[N_EDGES + e];
        if (d < N_NODES) atomicAdd(&g_cnt[d], 1);
    }
}

__global__ void k_dis() {
    int i = blockIdx.x * blockDim.x + threadIdx.x;
    if (i < N_NODES) g_dis[i] = rsqrtf((float)g_cnt[i] + 1.0f);
}

__global__ void k_scan1() {
    __shared__ int sm[1024];
    int i = blockIdx.x * 1024 + threadIdx.x;
    sm[threadIdx.x] = (i < N_NODES) ? g_cnt[i] : 0;
    __syncthreads();
#pragma unroll
    for (int off = 1; off < 1024; off <<= 1) {
        int t = (threadIdx.x >= off) ? sm[threadIdx.x - off] : 0;
        __syncthreads();
        sm[threadIdx.x] += t;
        __syncthreads();
    }
    if (i < N_NODES) g_incl[i] = sm[threadIdx.x];
    if (threadIdx.x == 1023) g_part[blockIdx.x] = sm[1023];
}

__global__ void k_scan2() {
    __shared__ int sm[128];
    int t = threadIdx.x;
    int v = (t < NB_SCAN) ? g_part[t] : 0;
    sm[t] = v;
    __syncthreads();
#pragma unroll
    for (int off = 1; off < 128; off <<= 1) {
        int u = (t >= off) ? sm[t - off] : 0;
        __syncthreads();
        sm[t] += u;
        __syncthreads();
    }
    g_partx[t] = sm[t] - v;  // exclusive
}

__global__ void k_scan3() {
    int i = blockIdx.x * blockDim.x + threadIdx.x;
    if (i < N_NODES) {
        int rs = g_incl[i] - g_cnt[i] + g_partx[i >> 10];
        g_row_start[i] = rs;
        g_cursor[i] = rs;
    }
    if (i == 0) g_row_start[N_NODES] = N_EDGES;
}

__global__ void k_fill(const int* __restrict__ ei) {
    int e = blockIdx.x * blockDim.x + threadIdx.x;
    if (e < N_EDGES) {
        unsigned s = (unsigned)ei[e];
        unsigned d = (unsigned)ei[N_EDGES + e];
        if (s < N_NODES && d < N_NODES) {
            int pos = atomicAdd(&g_cursor[d], 1);
            g_csr_src[pos] = s;
            g_csr_w[pos] = g_dis[s];
        }
    }
}

// ---------------- GEMM1: g0 = X @ W1 (f32x2, fp16 output) ----------------
__global__ void __launch_bounds__(256) k_gemm1(const float* __restrict__ X,
                                               const float* __restrict__ W) {
    __shared__ float xsT[128][64];
    const int tid = threadIdx.x;
    const int row0 = blockIdx.x * 64;

    {   // load + transpose X tile [64x128] into xsT[k][r] with segment swizzle
        int row = tid >> 2, seg = tid & 3;
        int gr = row0 + row;
        int rs = row ^ (seg << 3);
        if (gr < N_NODES) {
            const float4* xr = (const float4*)(X + (size_t)gr * 128 + seg * 32);
#pragma unroll
            for (int i = 0; i < 8; i++) {
                float4 v = xr[i];
                int c = seg * 32 + i * 4;
                xsT[c + 0][rs] = v.x; xsT[c + 1][rs] = v.y;
                xsT[c + 2][rs] = v.z; xsT[c + 3][rs] = v.w;
            }
        } else {
#pragma unroll
            for (int i = 0; i < 8; i++) {
                int c = seg * 32 + i * 4;
                xsT[c + 0][rs] = 0.f; xsT[c + 1][rs] = 0.f;
                xsT[c + 2][rs] = 0.f; xsT[c + 3][rs] = 0.f;
            }
        }
    }
    __syncthreads();

    const int ty = tid >> 5, lane = tid & 31, col = lane * 4;
    unsigned long long acc[4][4];
#pragma unroll
    for (int i = 0; i < 4; i++)
#pragma unroll
        for (int j = 0; j < 4; j++) acc[i][j] = 0ULL;

    for (int q = 0; q < 4; q++) {
        const int rb = ((ty ^ q) & 7) * 8;
#pragma unroll
        for (int kk = 0; kk < 32; kk++) {
            const int k = q * 32 + kk;
            ulonglong2 xa = *(const ulonglong2*)&xsT[k][rb];      // rows +0,+1 | +2,+3
            ulonglong2 xb = *(const ulonglong2*)&xsT[k][rb + 4];  // rows +4,+5 | +6,+7
            float4 wv = *(const float4*)(W + (size_t)k * 128 + col);
            unsigned long long w0, w1, w2, w3;
            PACK_BB(w0, wv.x); PACK_BB(w1, wv.y); PACK_BB(w2, wv.z); PACK_BB(w3, wv.w);
            FMA2(acc[0][0], xa.x, w0); FMA2(acc[0][1], xa.x, w1);
            FMA2(acc[0][2], xa.x, w2); FMA2(acc[0][3], xa.x, w3);
            FMA2(acc[1][0], xa.y, w0); FMA2(acc[1][1], xa.y, w1);
            FMA2(acc[1][2], xa.y, w2); FMA2(acc[1][3], xa.y, w3);
            FMA2(acc[2][0], xb.x, w0); FMA2(acc[2][1], xb.x, w1);
            FMA2(acc[2][2], xb.x, w2); FMA2(acc[2][3], xb.x, w3);
            FMA2(acc[3][0], xb.y, w0); FMA2(acc[3][1], xb.y, w1);
            FMA2(acc[3][2], xb.y, w2); FMA2(acc[3][3], xb.y, w3);
        }
    }

#pragma unroll
    for (int rp = 0; rp < 4; rp++) {
        float lo0, hi0, lo1, hi1, lo2, hi2, lo3, hi3;
        UNPACK2(lo0, hi0, acc[rp][0]); UNPACK2(lo1, hi1, acc[rp][1]);
        UNPACK2(lo2, hi2, acc[rp][2]); UNPACK2(lo3, hi3, acc[rp][3]);
        int r0 = row0 + ty * 8 + rp * 2;
        if (r0 < N_NODES) {
            uint2 p;
            *(__half2*)&p.x = __floats2half2_rn(lo0, lo1);
            *(__half2*)&p.y = __floats2half2_rn(lo2, lo3);
            *(uint2*)(g_g0h + (size_t)r0 * 128 + col) = p;
        }
        int r1 = r0 + 1;
        if (r1 < N_NODES) {
            uint2 p;
            *(__half2*)&p.x = __floats2half2_rn(hi0, hi1);
            *(__half2*)&p.y = __floats2half2_rn(hi2, hi3);
            *(uint2*)(g_g0h + (size_t)r1 * 128 + col) = p;
        }
    }
}

// ---- shared gather core: accumulate Agg terms for node w, features fo..fo+3
__device__ __forceinline__ float4 gather_node(const __half* __restrict__ fin,
                                              int w, int lane) {
    const int fo = lane * 4;
    int start = g_row_start[w];
    int end   = g_row_start[w + 1];
    float disd = g_dis[w];

    uint2 sp = *(const uint2*)(fin + (size_t)w * 128 + fo);
    float2 s01 = __half22float2(*(__half2*)&sp.x);
    float2 s23 = __half22float2(*(__half2*)&sp.y);
    float4 acc = make_float4(s01.x * disd, s01.y * disd, s23.x * disd, s23.y * disd);

    int j = start;
    for (; j + 8 <= end; j += 8) {
        int   ss[8];
        float ww[8];
#pragma unroll
        for (int u = 0; u < 8; u++) { ss[u] = g_csr_src[j + u]; ww[u] = g_csr_w[j + u]; }
        uint2 p[8];
#pragma unroll
        for (int u = 0; u < 8; u++)
            p[u] = *(const uint2*)(fin + (size_t)ss[u] * 128 + fo);
#pragma unroll
        for (int u = 0; u < 8; u++) {
            float2 a = __half22float2(*(__half2*)&p[u].x);
            float2 b = __half22float2(*(__half2*)&p[u].y);
            acc.x += a.x * ww[u]; acc.y += a.y * ww[u];
            acc.z += b.x * ww[u]; acc.w += b.y * ww[u];
        }
    }
    for (; j < end; j++) {
        int s = g_csr_src[j];
        float ws = g_csr_w[j];
        uint2 p = *(const uint2*)(fin + (size_t)s * 128 + fo);
        float2 a = __half22float2(*(__half2*)&p.x);
        float2 b = __half22float2(*(__half2*)&p.y);
        acc.x += a.x * ws; acc.y += a.y * ws; acc.z += b.x * ws; acc.w += b.y * ws;
    }

    acc.x *= disd; acc.y *= disd; acc.z *= disd; acc.w *= disd;
    return acc;
}

// ---------------- gather pass 0: h = half(Agg(g0) + b1) ----------------
__global__ void __launch_bounds__(256) k_gather0(const float* __restrict__ b1) {
    int w = (blockIdx.x * 256 + threadIdx.x) >> 5;
    if (w >= N_NODES) return;
    int lane = threadIdx.x & 31;
    const int fo = lane * 4;

    float4 acc = gather_node(g_g0h, w, lane);
    float4 bv = *(const float4*)(b1 + fo);
    acc.x += bv.x; acc.y += bv.y; acc.z += bv.z; acc.w += bv.w;
    uint2 p;
    *(__half2*)&p.x = __floats2half2_rn(acc.x, acc.y);
    *(__half2*)&p.y = __floats2half2_rn(acc.z, acc.w);
    *(uint2*)(g_hh + (size_t)w * 128 + fo) = p;
}

// ------- fused: ah = Agg(h) (smem), then mu/ls/z GEMM epilogue -------
#define XS 132  // row stride (floats); 132%32=4 spreads float4 stores over banks
__global__ void __launch_bounds__(256) k_gather_gemm2(const float* __restrict__ Wmu,
                                                      const float* __restrict__ bmu,
                                                      const float* __restrict__ Wls,
                                                      const float* __restrict__ bls,
                                                      const float* __restrict__ eps,
                                                      float* __restrict__ out) {
    __shared__ float xrm[64][XS];
    const int tid = threadIdx.x;
    const int g = tid >> 5, lane = tid & 31;
    const int row0 = blockIdx.x * 64;
    const int fo = lane * 4;

    // Phase 1: warp g gathers nodes row0 + g*8 .. +7 into smem row-major
#pragma unroll 1
    for (int i = 0; i < 8; i++) {
        int lr = g * 8 + i;
        int w = row0 + lr;
        float4 acc;
        if (w < N_NODES) acc = gather_node(g_hh, w, lane);
        else             acc = make_float4(0.f, 0.f, 0.f, 0.f);
        *(float4*)&xrm[lr][fo] = acc;
    }
    __syncthreads();

    // Phase 2: GEMM. thread = 8 rows x (2 mu cols + 2 ls cols), col-pair FFMA2
    const int rb = g * 8;
    const int jc = lane * 2;

    unsigned long long am[8], al[8];
#pragma unroll
    for (int i = 0; i < 8; i++) { am[i] = 0ULL; al[i] = 0ULL; }

    for (int k0 = 0; k0 < 128; k0 += 4) {
        float4 xv[8];
#pragma unroll
        for (int i = 0; i < 8; i++) xv[i] = *(const float4*)&xrm[rb + i][k0];
#pragma unroll
        for (int kk = 0; kk < 4; kk++) {
            unsigned long long wm = *(const unsigned long long*)(Wmu + (size_t)(k0 + kk) * 64 + jc);
            unsigned long long wl = *(const unsigned long long*)(Wls + (size_t)(k0 + kk) * 64 + jc);
#pragma unroll
            for (int i = 0; i < 8; i++) {
                float xs = (kk == 0) ? xv[i].x : (kk == 1) ? xv[i].y
                         : (kk == 2) ? xv[i].z : xv[i].w;
                unsigned long long xp;
                PACK_BB(xp, xs);
                FMA2(am[i], xp, wm);
                FMA2(al[i], xp, wl);
            }
        }
    }

    const size_t NOUT = (size_t)N_NODES * C_OUT;
    float bm0 = bmu[jc], bm1 = bmu[jc + 1];
    float bl0 = bls[jc], bl1 = bls[jc + 1];
#pragma unroll
    for (int i = 0; i < 8; i++) {
        int r = row0 + rb + i;
        if (r >= N_NODES) continue;
        float mu0, mu1, ls0, ls1;
        UNPACK2(mu0, mu1, am[i]);
        UNPACK2(ls0, ls1, al[i]);
        mu0 += bm0; mu1 += bm1; ls0 += bl0; ls1 += bl1;
        float2 ev = *(const float2*)(eps + (size_t)r * 64 + jc);
        float z0 = mu0 + ev.x * __expf(ls0);
        float z1 = mu1 + ev.y * __expf(ls1);
        size_t off = (size_t)r * 64 + jc;
        *(float2*)(out + off)            = make_float2(z0, z1);
        *(float2*)(out + NOUT + off)     = make_float2(mu0, mu1);
        *(float2*)(out + 2 * NOUT + off) = make_float2(ls0, ls1);
    }
}

extern "C" void kernel_launch(void* const* d_in, const int* in_sizes, int n_in,
                              void* d_out, int out_size) {
    const float* x   = (const float*)d_in[0];
    const int*   ei  = (const int*)d_in[1];   // int32 (JAX demotes int64)
    const float* W1  = (const float*)d_in[2];
    const float* b1  = (const float*)d_in[3];
    const float* Wmu = (const float*)d_in[4];
    const float* bmu = (const float*)d_in[5];
    const float* Wls = (const float*)d_in[6];
    const float* bls = (const float*)d_in[7];
    const float* eps = (const float*)d_in[8];
    float* out       = (float*)d_out;
    (void)in_sizes; (void)n_in; (void)out_size;

    k_zero_cnt<<<(N_NODES + 255) / 256, 256>>>();                 // 0
    k_hist<<<(N_EDGES + 255) / 256, 256>>>(ei);                   // 1
    k_dis<<<(N_NODES + 255) / 256, 256>>>();                      // 2
    k_gemm1<<<(N_NODES + 63) / 64, 256>>>(x, W1);                 // 3 <- profiled slot
    k_scan1<<<NB_SCAN, 1024>>>();                                 // 4
    k_scan2<<<1, 128>>>();                                        // 5
    k_scan3<<<(N_NODES + 255) / 256, 256>>>();                    // 6
    k_fill<<<(N_EDGES + 255) / 256, 256>>>(ei);                   // 7
    k_gather0<<<(N_NODES + 7) / 8, 256>>>(b1);                    // 8
    k_gather_gemm2<<<(N_NODES + 63) / 64, 256>>>(Wmu, bmu, Wls, bls, eps, out);  // 9
}

// round 8
// speedup vs baseline: 1.1394x; 1.1394x over previous
#include <cuda_runtime.h>
#include <cuda_fp16.h>

#define N_NODES 100000
#define N_EDGES 1600000
#define HID 128
#define C_OUT 64
#define NB_SCAN 98  // ceil(100000/1024)

// ---- scratch (__device__ globals; allocation-free rule) ----
__device__ __align__(16) float g_dis[N_NODES];
__device__ int   g_cnt[N_NODES];
__device__ int   g_cursor[N_NODES];
__device__ int   g_incl[N_NODES];
__device__ int   g_part[128];
__device__ int   g_partx[128];
__device__ int   g_row_start[N_NODES + 1];
__device__ int   g_csr_src[N_EDGES];
__device__ __align__(16) float  g_csr_w[N_EDGES];
__device__ __align__(16) __half g_g0h[(size_t)N_NODES * HID];  // x @ W1 (fp16)
__device__ __align__(16) __half g_hh [(size_t)N_NODES * HID];  // h      (fp16)
__device__ __align__(16) float  g_ah [(size_t)N_NODES * HID];  // Agg(h) (fp32)

// ---------- f32x2 helpers ----------
#define FMA2(d, a, b) asm("fma.rn.f32x2 %0, %1, %2, %0;" : "+l"(d) : "l"(a), "l"(b))
#define PACK_BB(d, f) asm("mov.b64 %0, {%1, %1};" : "=l"(d) : "f"(f))
#define UNPACK2(lo, hi, d) asm("mov.b64 {%0, %1}, %2;" : "=f"(lo), "=f"(hi) : "l"(d))

// ---------------- degree / CSR build ----------------
__global__ void k_zero_cnt() {
    int i = blockIdx.x * blockDim.x + threadIdx.x;
    if (i < N_NODES) g_cnt[i] = 0;
}

__global__ void k_hist(const int* __restrict__ ei) {
    int e = blockIdx.x * blockDim.x + threadIdx.x;
    if (e < N_EDGES) {
        unsigned d = (unsigned)ei[N_EDGES + e];
        if (d < N_NODES) atomicAdd(&g_cnt[d], 1);
    }
}

__global__ void k_dis() {
    int i = blockIdx.x * blockDim.x + threadIdx.x;
    if (i < N_NODES) g_dis[i] = rsqrtf((float)g_cnt[i] + 1.0f);
}

__global__ void k_scan1() {
    __shared__ int sm[1024];
    int i = blockIdx.x * 1024 + threadIdx.x;
    sm[threadIdx.x] = (i < N_NODES) ? g_cnt[i] : 0;
    __syncthreads();
#pragma unroll
    for (int off = 1; off < 1024; off <<= 1) {
        int t = (threadIdx.x >= off) ? sm[threadIdx.x - off] : 0;
        __syncthreads();
        sm[threadIdx.x] += t;
        __syncthreads();
    }
    if (i < N_NODES) g_incl[i] = sm[threadIdx.x];
    if (threadIdx.x == 1023) g_part[blockIdx.x] = sm[1023];
}

__global__ void k_scan2() {
    __shared__ int sm[128];
    int t = threadIdx.x;
    int v = (t < NB_SCAN) ? g_part[t] : 0;
    sm[t] = v;
    __syncthreads();
#pragma unroll
    for (int off = 1; off < 128; off <<= 1) {
        int u = (t >= off) ? sm[t - off] : 0;
        __syncthreads();
        sm[t] += u;
        __syncthreads();
    }
    g_partx[t] = sm[t] - v;  // exclusive
}

__global__ void k_scan3() {
    int i = blockIdx.x * blockDim.x + threadIdx.x;
    if (i < N_NODES) {
        int rs = g_incl[i] - g_cnt[i] + g_partx[i >> 10];
        g_row_start[i] = rs;
        g_cursor[i] = rs;
    }
    if (i == 0) g_row_start[N_NODES] = N_EDGES;
}

__global__ void k_fill(const int* __restrict__ ei) {
    int e = blockIdx.x * blockDim.x + threadIdx.x;
    if (e < N_EDGES) {
        unsigned s = (unsigned)ei[e];
        unsigned d = (unsigned)ei[N_EDGES + e];
        if (s < N_NODES && d < N_NODES) {
            int pos = atomicAdd(&g_cursor[d], 1);
            g_csr_src[pos] = s;
            g_csr_w[pos] = g_dis[s];
        }
    }
}

// ---- shared tile loader: X tile [64 x 128] -> xsT[k][row^] (swizzled stores)
__device__ __forceinline__ void load_tileT(float (*xsT)[64],
                                           const float* __restrict__ src,
                                           int row0, int tid) {
    int row = tid >> 2, seg = tid & 3;
    int gr = row0 + row;
    int rs = row ^ (seg << 3);  // swizzle avoids 4-way store conflicts
    if (gr < N_NODES) {
        const float4* xr = (const float4*)(src + (size_t)gr * 128 + seg * 32);
#pragma unroll
        for (int i = 0; i < 8; i++) {
            float4 v = xr[i];
            int c = seg * 32 + i * 4;
            xsT[c + 0][rs] = v.x; xsT[c + 1][rs] = v.y;
            xsT[c + 2][rs] = v.z; xsT[c + 3][rs] = v.w;
        }
    } else {
#pragma unroll
        for (int i = 0; i < 8; i++) {
            int c = seg * 32 + i * 4;
            xsT[c + 0][rs] = 0.f; xsT[c + 1][rs] = 0.f;
            xsT[c + 2][rs] = 0.f; xsT[c + 3][rs] = 0.f;
        }
    }
}

// ---------------- GEMM1 v2: g0 = X @ W1, broadcast-x layout ----------------
// Warp ty owns rows ty*8..+7, all 128 cols. Per k: x via 2 broadcast LDS.128
// (32B/warp), W via one coalesced float4 LDG (L1-hot). 16 FMA2/thread/k.
__global__ void __launch_bounds__(256) k_gemm1(const float* __restrict__ X,
                                               const float* __restrict__ W) {
    __shared__ float xsT[128][64];
    const int tid = threadIdx.x;
    const int row0 = blockIdx.x * 64;

    load_tileT(xsT, X, row0, tid);
    __syncthreads();

    const int ty = tid >> 5, lane = tid & 31, col = lane * 4;
    unsigned long long acc[8][2];  // [row][col-pair]
#pragma unroll
    for (int i = 0; i < 8; i++) { acc[i][0] = 0ULL; acc[i][1] = 0ULL; }

    for (int q = 0; q < 4; q++) {
        const int rb = ((ty ^ q) & 7) * 8;  // physical rows for logical ty*8..+7
#pragma unroll
        for (int kk = 0; kk < 32; kk++) {
            const int k = q * 32 + kk;
            float4 xa = *(const float4*)&xsT[k][rb];      // rows 0-3 (broadcast)
            float4 xb = *(const float4*)&xsT[k][rb + 4];  // rows 4-7 (broadcast)
            ulonglong2 wv = *(const ulonglong2*)(W + (size_t)k * 128 + col);
            float xr[8] = {xa.x, xa.y, xa.z, xa.w, xb.x, xb.y, xb.z, xb.w};
#pragma unroll
            for (int i = 0; i < 8; i++) {
                unsigned long long xp;
                PACK_BB(xp, xr[i]);
                FMA2(acc[i][0], xp, wv.x);
                FMA2(acc[i][1], xp, wv.y);
            }
        }
    }

#pragma unroll
    for (int i = 0; i < 8; i++) {
        int r = row0 + ty * 8 + i;
        if (r < N_NODES) {
            float c0, c1, c2, c3;
            UNPACK2(c0, c1, acc[i][0]);
            UNPACK2(c2, c3, acc[i][1]);
            uint2 p;
            *(__half2*)&p.x = __floats2half2_rn(c0, c1);
            *(__half2*)&p.y = __floats2half2_rn(c2, c3);
            *(uint2*)(g_g0h + (size_t)r * 128 + col) = p;
        }
    }
}

// ---- gather core (R5 proven, MLP-4): Agg terms for node w, feats lane*4..+3
__device__ __forceinline__ float4 gather_node(const __half* __restrict__ fin,
                                              int w, int lane) {
    const int fo = lane * 4;
    int start = g_row_start[w];
    int end   = g_row_start[w + 1];
    float disd = g_dis[w];

    uint2 sp = *(const uint2*)(fin + (size_t)w * 128 + fo);
    float2 s01 = __half22float2(*(__half2*)&sp.x);
    float2 s23 = __half22float2(*(__half2*)&sp.y);
    float4 acc = make_float4(s01.x * disd, s01.y * disd, s23.x * disd, s23.y * disd);

    int j = start;
    for (; j + 4 <= end; j += 4) {
        int s0 = g_csr_src[j + 0], s1 = g_csr_src[j + 1];
        int s2 = g_csr_src[j + 2], s3 = g_csr_src[j + 3];
        float w0 = g_csr_w[j + 0], w1 = g_csr_w[j + 1];
        float w2 = g_csr_w[j + 2], w3 = g_csr_w[j + 3];
        uint2 p0 = *(const uint2*)(fin + (size_t)s0 * 128 + fo);
        uint2 p1 = *(const uint2*)(fin + (size_t)s1 * 128 + fo);
        uint2 p2 = *(const uint2*)(fin + (size_t)s2 * 128 + fo);
        uint2 p3 = *(const uint2*)(fin + (size_t)s3 * 128 + fo);
        {
            float2 a = __half22float2(*(__half2*)&p0.x), b = __half22float2(*(__half2*)&p0.y);
            acc.x += a.x * w0; acc.y += a.y * w0; acc.z += b.x * w0; acc.w += b.y * w0;
        }
        {
            float2 a = __half22float2(*(__half2*)&p1.x), b = __half22float2(*(__half2*)&p1.y);
            acc.x += a.x * w1; acc.y += a.y * w1; acc.z += b.x * w1; acc.w += b.y * w1;
        }
        {
            float2 a = __half22float2(*(__half2*)&p2.x), b = __half22float2(*(__half2*)&p2.y);
            acc.x += a.x * w2; acc.y += a.y * w2; acc.z += b.x * w2; acc.w += b.y * w2;
        }
        {
            float2 a = __half22float2(*(__half2*)&p3.x), b = __half22float2(*(__half2*)&p3.y);
            acc.x += a.x * w3; acc.y += a.y * w3; acc.z += b.x * w3; acc.w += b.y * w3;
        }
    }
    for (; j < end; j++) {
        int s = g_csr_src[j];
        float ws = g_csr_w[j];
        uint2 p = *(const uint2*)(fin + (size_t)s * 128 + fo);
        float2 a = __half22float2(*(__half2*)&p.x), b = __half22float2(*(__half2*)&p.y);
        acc.x += a.x * ws; acc.y += a.y * ws; acc.z += b.x * ws; acc.w += b.y * ws;
    }

    acc.x *= disd; acc.y *= disd; acc.z *= disd; acc.w *= disd;
    return acc;
}

// PASS 0: h = half(Agg(g0) + b1) ; PASS 1: ah = float(Agg(h))
template <int PASS>
__global__ void __launch_bounds__(256) k_gather(const float* __restrict__ b1) {
    int w = (blockIdx.x * 256 + threadIdx.x) >> 5;
    if (w >= N_NODES) return;
    int lane = threadIdx.x & 31;
    const int fo = lane * 4;

    float4 acc = gather_node((PASS == 0) ? g_g0h : g_hh, w, lane);
    if (PASS == 0) {
        float4 bv = *(const float4*)(b1 + fo);
        acc.x += bv.x; acc.y += bv.y; acc.z += bv.z; acc.w += bv.w;
        uint2 p;
        *(__half2*)&p.x = __floats2half2_rn(acc.x, acc.y);
        *(__half2*)&p.y = __floats2half2_rn(acc.z, acc.w);
        *(uint2*)(g_hh + (size_t)w * 128 + fo) = p;
    } else {
        *(float4*)(g_ah + (size_t)w * 128 + fo) = acc;
    }
}

// ---------------- GEMM2 v2 + epilogue: broadcast-x layout ----------------
// Warp ty owns rows ty*8..+7; thread cols jc=lane*2 for BOTH mu and ls.
__global__ void __launch_bounds__(256) k_gemm2(const float* __restrict__ Wmu,
                                               const float* __restrict__ bmu,
                                               const float* __restrict__ Wls,
                                               const float* __restrict__ bls,
                                               const float* __restrict__ eps,
                                               float* __restrict__ out) {
    __shared__ float xsT[128][64];
    const int tid = threadIdx.x;
    const int row0 = blockIdx.x * 64;

    load_tileT(xsT, g_ah, row0, tid);
    __syncthreads();

    const int ty = tid >> 5, lane = tid & 31, jc = lane * 2;
    unsigned long long am[8], al[8];
#pragma unroll
    for (int i = 0; i < 8; i++) { am[i] = 0ULL; al[i] = 0ULL; }

    for (int q = 0; q < 4; q++) {
        const int rb = ((ty ^ q) & 7) * 8;
#pragma unroll
        for (int kk = 0; kk < 32; kk++) {
            const int k = q * 32 + kk;
            float4 xa = *(const float4*)&xsT[k][rb];
            float4 xb = *(const float4*)&xsT[k][rb + 4];
            unsigned long long wm = *(const unsigned long long*)(Wmu + (size_t)k * 64 + jc);
            unsigned long long wl = *(const unsigned long long*)(Wls + (size_t)k * 64 + jc);
            float xr[8] = {xa.x, xa.y, xa.z, xa.w, xb.x, xb.y, xb.z, xb.w};
#pragma unroll
            for (int i = 0; i < 8; i++) {
                unsigned long long xp;
                PACK_BB(xp, xr[i]);
                FMA2(am[i], xp, wm);
                FMA2(al[i], xp, wl);
            }
        }
    }

    const size_t NOUT = (size_t)N_NODES * C_OUT;
    float bm0 = bmu[jc], bm1 = bmu[jc + 1];
    float bl0 = bls[jc], bl1 = bls[jc + 1];
#pragma unroll
    for (int i = 0; i < 8; i++) {
        int r = row0 + ty * 8 + i;
        if (r >= N_NODES) continue;
        float mu0, mu1, ls0, ls1;
        UNPACK2(mu0, mu1, am[i]);
        UNPACK2(ls0, ls1, al[i]);
        mu0 += bm0; mu1 += bm1; ls0 += bl0; ls1 += bl1;
        float2 ev = *(const float2*)(eps + (size_t)r * 64 + jc);
        float z0 = mu0 + ev.x * __expf(ls0);
        float z1 = mu1 + ev.y * __expf(ls1);
        size_t off = (size_t)r * 64 + jc;
        *(float2*)(out + off)            = make_float2(z0, z1);
        *(float2*)(out + NOUT + off)     = make_float2(mu0, mu1);
        *(float2*)(out + 2 * NOUT + off) = make_float2(ls0, ls1);
    }
}

extern "C" void kernel_launch(void* const* d_in, const int* in_sizes, int n_in,
                              void* d_out, int out_size) {
    const float* x   = (const float*)d_in[0];
    const int*   ei  = (const int*)d_in[1];   // int32 (JAX demotes int64)
    const float* W1  = (const float*)d_in[2];
    const float* b1  = (const float*)d_in[3];
    const float* Wmu = (const float*)d_in[4];
    const float* bmu = (const float*)d_in[5];
    const float* Wls = (const float*)d_in[6];
    const float* bls = (const float*)d_in[7];
    const float* eps = (const float*)d_in[8];
    float* out       = (float*)d_out;
    (void)in_sizes; (void)n_in; (void)out_size;

    k_zero_cnt<<<(N_NODES + 255) / 256, 256>>>();                 // 0
    k_hist<<<(N_EDGES + 255) / 256, 256>>>(ei);                   // 1
    k_dis<<<(N_NODES + 255) / 256, 256>>>();                      // 2
    k_gemm1<<<(N_NODES + 63) / 64, 256>>>(x, W1);                 // 3 <- profiled slot
    k_scan1<<<NB_SCAN, 1024>>>();                                 // 4
    k_scan2<<<1, 128>>>();                                        // 5
    k_scan3<<<(N_NODES + 255) / 256, 256>>>();                    // 6
    k_fill<<<(N_EDGES + 255) / 256, 256>>>(ei);                   // 7
    k_gather<0><<<(N_NODES + 7) / 8, 256>>>(b1);                  // 8
    k_gather<1><<<(N_NODES + 7) / 8, 256>>>(b1);                  // 9
    k_gemm2<<<(N_NODES + 63) / 64, 256>>>(Wmu, bmu, Wls, bls, eps, out);  // 10
}

// round 9
// speedup vs baseline: 1.2801x; 1.1235x over previous
#include <cuda_runtime.h>
#include <cuda_fp16.h>

#define N_NODES 100000
#define N_EDGES 1600000
#define HID 128
#define C_OUT 64
#define NB_SCAN 98  // ceil(100000/1024)

// ---- scratch (__device__ globals; allocation-free rule) ----
__device__ __align__(16) float g_dis[N_NODES];
__device__ int   g_cnt[N_NODES];
__device__ int   g_cursor[N_NODES];
__device__ int   g_incl[N_NODES];
__device__ int   g_part[128];
__device__ int   g_partx[128];
__device__ int   g_row_start[N_NODES + 1];
__device__ int   g_csr_src[N_EDGES];
__device__ __align__(16) __half g_G[(size_t)N_NODES * HID];  // dis * (x@W1)   (fp16)
__device__ __align__(16) __half g_H[(size_t)N_NODES * HID];  // dis * h        (fp16)
__device__ __align__(16) __half g_A[(size_t)N_NODES * HID];  // ah = Agg(h)    (fp16)

// ---------- f32x2 helpers ----------
#define FMA2(d, a, b) asm("fma.rn.f32x2 %0, %1, %2, %0;" : "+l"(d) : "l"(a), "l"(b))
#define PACK_BB(d, f) asm("mov.b64 %0, {%1, %1};" : "=l"(d) : "f"(f))
#define UNPACK2(lo, hi, d) asm("mov.b64 {%0, %1}, %2;" : "=f"(lo), "=f"(hi) : "l"(d))

// ---------------- degree / CSR build ----------------
__global__ void k_zero_cnt() {
    int i = blockIdx.x * blockDim.x + threadIdx.x;
    if (i < N_NODES) g_cnt[i] = 0;
}

__global__ void k_hist(const int* __restrict__ ei) {
    int e = blockIdx.x * blockDim.x + threadIdx.x;
    if (e < N_EDGES) {
        unsigned d = (unsigned)ei[N_EDGES + e];
        if (d < N_NODES) atomicAdd(&g_cnt[d], 1);
    }
}

__global__ void k_dis() {
    int i = blockIdx.x * blockDim.x + threadIdx.x;
    if (i < N_NODES) g_dis[i] = rsqrtf((float)g_cnt[i] + 1.0f);
}

__global__ void k_scan1() {
    __shared__ int sm[1024];
    int i = blockIdx.x * 1024 + threadIdx.x;
    sm[threadIdx.x] = (i < N_NODES) ? g_cnt[i] : 0;
    __syncthreads();
#pragma unroll
    for (int off = 1; off < 1024; off <<= 1) {
        int t = (threadIdx.x >= off) ? sm[threadIdx.x - off] : 0;
        __syncthreads();
        sm[threadIdx.x] += t;
        __syncthreads();
    }
    if (i < N_NODES) g_incl[i] = sm[threadIdx.x];
    if (threadIdx.x == 1023) g_part[blockIdx.x] = sm[1023];
}

__global__ void k_scan2() {
    __shared__ int sm[128];
    int t = threadIdx.x;
    int v = (t < NB_SCAN) ? g_part[t] : 0;
    sm[t] = v;
    __syncthreads();
#pragma unroll
    for (int off = 1; off < 128; off <<= 1) {
        int u = (t >= off) ? sm[t - off] : 0;
        __syncthreads();
        sm[t] += u;
        __syncthreads();
    }
    g_partx[t] = sm[t] - v;  // exclusive
}

__global__ void k_scan3() {
    int i = blockIdx.x * blockDim.x + threadIdx.x;
    if (i < N_NODES) {
        int rs = g_incl[i] - g_cnt[i] + g_partx[i >> 10];
        g_row_start[i] = rs;
        g_cursor[i] = rs;
    }
    if (i == 0) g_row_start[N_NODES] = N_EDGES;
}

__global__ void k_fill(const int* __restrict__ ei) {
    int e = blockIdx.x * blockDim.x + threadIdx.x;
    if (e < N_EDGES) {
        unsigned s = (unsigned)ei[e];
        unsigned d = (unsigned)ei[N_EDGES + e];
        if (s < N_NODES && d < N_NODES) {
            int pos = atomicAdd(&g_cursor[d], 1);
            g_csr_src[pos] = s;
        }
    }
}

// ---- shared tile loaders: [64 x 128] -> xsT[k][row^] (swizzled stores) ----
__device__ __forceinline__ void load_tileT_f32(float (*xsT)[64],
                                               const float* __restrict__ src,
                                               int row0, int tid) {
    int row = tid >> 2, seg = tid & 3;
    int gr = row0 + row;
    int rs = row ^ (seg << 3);
    if (gr < N_NODES) {
        const float4* xr = (const float4*)(src + (size_t)gr * 128 + seg * 32);
#pragma unroll
        for (int i = 0; i < 8; i++) {
            float4 v = xr[i];
            int c = seg * 32 + i * 4;
            xsT[c + 0][rs] = v.x; xsT[c + 1][rs] = v.y;
            xsT[c + 2][rs] = v.z; xsT[c + 3][rs] = v.w;
        }
    } else {
#pragma unroll
        for (int i = 0; i < 8; i++) {
            int c = seg * 32 + i * 4;
            xsT[c + 0][rs] = 0.f; xsT[c + 1][rs] = 0.f;
            xsT[c + 2][rs] = 0.f; xsT[c + 3][rs] = 0.f;
        }
    }
}

__device__ __forceinline__ void load_tileT_f16(float (*xsT)[64],
                                               const __half* __restrict__ src,
                                               int row0, int tid) {
    int row = tid >> 2, seg = tid & 3;
    int gr = row0 + row;
    int rs = row ^ (seg << 3);
    if (gr < N_NODES) {
        const uint2* xr = (const uint2*)(src + (size_t)gr * 128 + seg * 32);
#pragma unroll
        for (int i = 0; i < 8; i++) {
            uint2 pv = xr[i];
            float2 a = __half22float2(*(__half2*)&pv.x);
            float2 b = __half22float2(*(__half2*)&pv.y);
            int c = seg * 32 + i * 4;
            xsT[c + 0][rs] = a.x; xsT[c + 1][rs] = a.y;
            xsT[c + 2][rs] = b.x; xsT[c + 3][rs] = b.y;
        }
    } else {
#pragma unroll
        for (int i = 0; i < 8; i++) {
            int c = seg * 32 + i * 4;
            xsT[c + 0][rs] = 0.f; xsT[c + 1][rs] = 0.f;
            xsT[c + 2][rs] = 0.f; xsT[c + 3][rs] = 0.f;
        }
    }
}

// ---------------- GEMM1: G = fp16(dis * (X @ W1)) ----------------
// Warp ty owns rows ty*8..+7, all 128 cols; x broadcast from smem, W via LDG.
__global__ void __launch_bounds__(256, 4) k_gemm1(const float* __restrict__ X,
                                                  const float* __restrict__ W) {
    __shared__ float xsT[128][64];
    const int tid = threadIdx.x;
    const int row0 = blockIdx.x * 64;

    load_tileT_f32(xsT, X, row0, tid);
    __syncthreads();

    const int ty = tid >> 5, lane = tid & 31, col = lane * 4;
    unsigned long long acc[8][2];  // [row][col-pair]
#pragma unroll
    for (int i = 0; i < 8; i++) { acc[i][0] = 0ULL; acc[i][1] = 0ULL; }

    for (int q = 0; q < 4; q++) {
        const int rb = ((ty ^ q) & 7) * 8;
#pragma unroll
        for (int kk = 0; kk < 32; kk++) {
            const int k = q * 32 + kk;
            float4 xa = *(const float4*)&xsT[k][rb];
            float4 xb = *(const float4*)&xsT[k][rb + 4];
            ulonglong2 wv = *(const ulonglong2*)(W + (size_t)k * 128 + col);
            float xr[8] = {xa.x, xa.y, xa.z, xa.w, xb.x, xb.y, xb.z, xb.w};
#pragma unroll
            for (int i = 0; i < 8; i++) {
                unsigned long long xp;
                PACK_BB(xp, xr[i]);
                FMA2(acc[i][0], xp, wv.x);
                FMA2(acc[i][1], xp, wv.y);
            }
        }
    }

#pragma unroll
    for (int i = 0; i < 8; i++) {
        int r = row0 + ty * 8 + i;
        if (r < N_NODES) {
            float dv = g_dis[r];
            float c0, c1, c2, c3;
            UNPACK2(c0, c1, acc[i][0]);
            UNPACK2(c2, c3, acc[i][1]);
            uint2 p;
            *(__half2*)&p.x = __floats2half2_rn(c0 * dv, c1 * dv);
            *(__half2*)&p.y = __floats2half2_rn(c2 * dv, c3 * dv);
            *(uint2*)(g_G + (size_t)r * 128 + col) = p;
        }
    }
}

// ---- weight-free gather: acc = F[w] + sum_j F[src_j], feats lane*4..+3 ----
__device__ __forceinline__ float4 gather_node(const __half* __restrict__ fin,
                                              int w, int lane) {
    const int fo = lane * 4;
    int start = g_row_start[w];
    int end   = g_row_start[w + 1];

    uint2 sp = *(const uint2*)(fin + (size_t)w * 128 + fo);
    float2 s01 = __half22float2(*(__half2*)&sp.x);
    float2 s23 = __half22float2(*(__half2*)&sp.y);
    float4 acc = make_float4(s01.x, s01.y, s23.x, s23.y);

    int j = start;
    for (; j + 4 <= end; j += 4) {
        int s0 = g_csr_src[j + 0], s1 = g_csr_src[j + 1];
        int s2 = g_csr_src[j + 2], s3 = g_csr_src[j + 3];
        uint2 p0 = *(const uint2*)(fin + (size_t)s0 * 128 + fo);
        uint2 p1 = *(const uint2*)(fin + (size_t)s1 * 128 + fo);
        uint2 p2 = *(const uint2*)(fin + (size_t)s2 * 128 + fo);
        uint2 p3 = *(const uint2*)(fin + (size_t)s3 * 128 + fo);
        {
            float2 a = __half22float2(*(__half2*)&p0.x), b = __half22float2(*(__half2*)&p0.y);
            acc.x += a.x; acc.y += a.y; acc.z += b.x; acc.w += b.y;
        }
        {
            float2 a = __half22float2(*(__half2*)&p1.x), b = __half22float2(*(__half2*)&p1.y);
            acc.x += a.x; acc.y += a.y; acc.z += b.x; acc.w += b.y;
        }
        {
            float2 a = __half22float2(*(__half2*)&p2.x), b = __half22float2(*(__half2*)&p2.y);
            acc.x += a.x; acc.y += a.y; acc.z += b.x; acc.w += b.y;
        }
        {
            float2 a = __half22float2(*(__half2*)&p3.x), b = __half22float2(*(__half2*)&p3.y);
            acc.x += a.x; acc.y += a.y; acc.z += b.x; acc.w += b.y;
        }
    }
    for (; j < end; j++) {
        int s = g_csr_src[j];
        uint2 p = *(const uint2*)(fin + (size_t)s * 128 + fo);
        float2 a = __half22float2(*(__half2*)&p.x), b = __half22float2(*(__half2*)&p.y);
        acc.x += a.x; acc.y += a.y; acc.z += b.x; acc.w += b.y;
    }
    return acc;
}

// PASS 0: H = fp16( dis_w * (b1 + dis_w * acc_G) )
// PASS 1: A = fp16( dis_w * acc_H )
template <int PASS>
__global__ void __launch_bounds__(256) k_gather(const float* __restrict__ b1) {
    int w = (blockIdx.x * 256 + threadIdx.x) >> 5;
    if (w >= N_NODES) return;
    int lane = threadIdx.x & 31;
    const int fo = lane * 4;
    float disd = g_dis[w];

    float4 acc = gather_node((PASS == 0) ? g_G : g_H, w, lane);
    uint2 p;
    if (PASS == 0) {
        float4 bv = *(const float4*)(b1 + fo);
        // H = dis*(b1 + dis*acc)
        float h0 = disd * (bv.x + disd * acc.x);
        float h1 = disd * (bv.y + disd * acc.y);
        float h2 = disd * (bv.z + disd * acc.z);
        float h3 = disd * (bv.w + disd * acc.w);
        *(__half2*)&p.x = __floats2half2_rn(h0, h1);
        *(__half2*)&p.y = __floats2half2_rn(h2, h3);
        *(uint2*)(g_H + (size_t)w * 128 + fo) = p;
    } else {
        *(__half2*)&p.x = __floats2half2_rn(disd * acc.x, disd * acc.y);
        *(__half2*)&p.y = __floats2half2_rn(disd * acc.z, disd * acc.w);
        *(uint2*)(g_A + (size_t)w * 128 + fo) = p;
    }
}

// ---------------- GEMM2 + epilogue (ah tile fp16 -> fp32 smem) -------------
__global__ void __launch_bounds__(256, 4) k_gemm2(const float* __restrict__ Wmu,
                                                  const float* __restrict__ bmu,
                                                  const float* __restrict__ Wls,
                                                  const float* __restrict__ bls,
                                                  const float* __restrict__ eps,
                                                  float* __restrict__ out) {
    __shared__ float xsT[128][64];
    const int tid = threadIdx.x;
    const int row0 = blockIdx.x * 64;

    load_tileT_f16(xsT, g_A, row0, tid);
    __syncthreads();

    const int ty = tid >> 5, lane = tid & 31, jc = lane * 2;
    unsigned long long am[8], al[8];
#pragma unroll
    for (int i = 0; i < 8; i++) { am[i] = 0ULL; al[i] = 0ULL; }

    for (int q = 0; q < 4; q++) {
        const int rb = ((ty ^ q) & 7) * 8;
#pragma unroll
        for (int kk = 0; kk < 32; kk++) {
            const int k = q * 32 + kk;
            float4 xa = *(const float4*)&xsT[k][rb];
            float4 xb = *(const float4*)&xsT[k][rb + 4];
            unsigned long long wm = *(const unsigned long long*)(Wmu + (size_t)k * 64 + jc);
            unsigned long long wl = *(const unsigned long long*)(Wls + (size_t)k * 64 + jc);
            float xr[8] = {xa.x, xa.y, xa.z, xa.w, xb.x, xb.y, xb.z, xb.w};
#pragma unroll
            for (int i = 0; i < 8; i++) {
                unsigned long long xp;
                PACK_BB(xp, xr[i]);
                FMA2(am[i], xp, wm);
                FMA2(al[i], xp, wl);
            }
        }
    }

    const size_t NOUT = (size_t)N_NODES * C_OUT;
    float bm0 = bmu[jc], bm1 = bmu[jc + 1];
    float bl0 = bls[jc], bl1 = bls[jc + 1];
#pragma unroll
    for (int i = 0; i < 8; i++) {
        int r = row0 + ty * 8 + i;
        if (r >= N_NODES) continue;
        float mu0, mu1, ls0, ls1;
        UNPACK2(mu0, mu1, am[i]);
        UNPACK2(ls0, ls1, al[i]);
        mu0 += bm0; mu1 += bm1; ls0 += bl0; ls1 += bl1;
        float2 ev = *(const float2*)(eps + (size_t)r * 64 + jc);
        float z0 = mu0 + ev.x * __expf(ls0);
        float z1 = mu1 + ev.y * __expf(ls1);
        size_t off = (size_t)r * 64 + jc;
        *(float2*)(out + off)            = make_float2(z0, z1);
        *(float2*)(out + NOUT + off)     = make_float2(mu0, mu1);
        *(float2*)(out + 2 * NOUT + off) = make_float2(ls0, ls1);
    }
}

extern "C" void kernel_launch(void* const* d_in, const int* in_sizes, int n_in,
                              void* d_out, int out_size) {
    const float* x   = (const float*)d_in[0];
    const int*   ei  = (const int*)d_in[1];   // int32 (JAX demotes int64)
    const float* W1  = (const float*)d_in[2];
    const float* b1  = (const float*)d_in[3];
    const float* Wmu = (const float*)d_in[4];
    const float* bmu = (const float*)d_in[5];
    const float* Wls = (const float*)d_in[6];
    const float* bls = (const float*)d_in[7];
    const float* eps = (const float*)d_in[8];
    float* out       = (float*)d_out;
    (void)in_sizes; (void)n_in; (void)out_size;

    k_zero_cnt<<<(N_NODES + 255) / 256, 256>>>();                 // 0
    k_hist<<<(N_EDGES + 255) / 256, 256>>>(ei);                   // 1
    k_dis<<<(N_NODES + 255) / 256, 256>>>();                      // 2
    k_gemm1<<<(N_NODES + 63) / 64, 256>>>(x, W1);                 // 3 <- profiled slot
    k_scan1<<<NB_SCAN, 1024>>>();                                 // 4
    k_scan2<<<1, 128>>>();                                        // 5
    k_scan3<<<(N_NODES + 255) / 256, 256>>>();                    // 6
    k_fill<<<(N_EDGES + 255) / 256, 256>>>(ei);                   // 7
    k_gather<0><<<(N_NODES + 7) / 8, 256>>>(b1);                  // 8
    k_gather<1><<<(N_NODES + 7) / 8, 256>>>(b1);                  // 9
    k_gemm2<<<(N_NODES + 63) / 64, 256>>>(Wmu, bmu, Wls, bls, eps, out);  // 10
}